// round 6
// baseline (speedup 1.0000x reference)
#include <cuda_runtime.h>
#include <cuda_bf16.h>
#include <cstdint>

// Problem dims
#define BB 8
#define SS 1024          // IMG*IMG
#define EE 768           // D_EMBED == D_MODEL
#define NH 12
#define DD 64

// ---------------- scratch (device globals; no allocs allowed) ----------------
__device__ float g_q[BB * SS * EE];
__device__ float g_k[BB * SS * EE];
__device__ float g_v[BB * SS * EE];
__device__ float g_ctx[BB * SS * EE];

// =============================================================================
// tf32 helpers
// =============================================================================
__device__ __forceinline__ void split_tf32(float x, uint32_t& hi, uint32_t& lo) {
    asm("cvt.rna.tf32.f32 %0, %1;" : "=r"(hi) : "f"(x));
    float r = x - __uint_as_float(hi);
    asm("cvt.rna.tf32.f32 %0, %1;" : "=r"(lo) : "f"(r));
}
__device__ __forceinline__ void split_tf32_f(float x, float& hi, float& lo) {
    uint32_t h, l; split_tf32(x, h, l);
    hi = __uint_as_float(h); lo = __uint_as_float(l);
}

__device__ __forceinline__ void mma_tf32(float* d, const uint32_t* a, const uint32_t* b) {
    asm volatile(
        "mma.sync.aligned.m16n8k8.row.col.f32.tf32.tf32.f32 "
        "{%0,%1,%2,%3}, {%4,%5,%6,%7}, {%8,%9}, {%0,%1,%2,%3};"
        : "+f"(d[0]), "+f"(d[1]), "+f"(d[2]), "+f"(d[3])
        : "r"(a[0]), "r"(a[1]), "r"(a[2]), "r"(a[3]),
          "r"(b[0]), "r"(b[1]));
}
#define F2U(p) (*(const uint32_t*)&(p))

// =============================================================================
// Kernel 1: QKV projection, 3xtf32 mma, DOUBLE-BUFFERED k-loop.
//   Y[s,o] = sum_c X[b][c][s] * W[o][c] + bias[o]
// Stage (per buffer): AH/AL [32k][128m] pitch 136, BH/BL [64n][32k] pitch 36.
// =============================================================================
#define GP_AP 136
#define GP_BP 36
#define GP_AHo 0
#define GP_ALo 4352
#define GP_BHo 8704
#define GP_BLo 11008
#define GP_STAGE 13312
#define GP_SMEM_BYTES (2 * GP_STAGE * 4)   // 106496

__global__ __launch_bounds__(256) void proj_mma_kernel(
    const float* __restrict__ xq, const float* __restrict__ xk, const float* __restrict__ xv,
    const float* __restrict__ wq, const float* __restrict__ wk, const float* __restrict__ wv,
    const float* __restrict__ bq, const float* __restrict__ bk, const float* __restrict__ bv)
{
    extern __shared__ float sp[];

    const int mat = blockIdx.z >> 3;
    const int b   = blockIdx.z & 7;

    const float* x; const float* w; const float* bi; float* y;
    if (mat == 0)      { x = xq; w = wq; bi = bq; y = g_q; }
    else if (mat == 1) { x = xk; w = wk; bi = bk; y = g_k; }
    else               { x = xv; w = wv; bi = bv; y = g_v; }
    x += (size_t)b * EE * SS;
    y += (size_t)b * SS * EE;

    const int m0 = blockIdx.x * 128;
    const int n0 = blockIdx.y * 64;

    const int tid  = threadIdx.x;
    const int lane = tid & 31;
    const int w8   = tid >> 5;
    const int wm   = w8 >> 1;
    const int wn   = w8 & 1;
    const int gid  = lane >> 2;
    const int ctid = lane & 3;

    float4 ra[4], rb[2];

    auto prefetch = [&](int kg) {
        #pragma unroll
        for (int p = 0; p < 4; p++) {
            int idx = tid + p * 256;
            int kr  = idx >> 5;
            int mc  = (idx & 31) << 2;
            ra[p] = *(const float4*)(x + (size_t)(kg + kr) * SS + m0 + mc);
        }
        #pragma unroll
        for (int p = 0; p < 2; p++) {
            int idx = tid + p * 256;
            int r   = idx >> 3;
            int kc  = (idx & 7) << 2;
            rb[p] = *(const float4*)(w + (size_t)(n0 + r) * EE + kg + kc);
        }
    };
    auto stage_store = [&](int buf) {
        float* AH = sp + buf * GP_STAGE + GP_AHo;
        float* AL = sp + buf * GP_STAGE + GP_ALo;
        float* BH = sp + buf * GP_STAGE + GP_BHo;
        float* BL = sp + buf * GP_STAGE + GP_BLo;
        #pragma unroll
        for (int p = 0; p < 4; p++) {
            int idx = tid + p * 256;
            int kr  = idx >> 5;
            int mc  = (idx & 31) << 2;
            float h, l;
            split_tf32_f(ra[p].x, h, l); AH[kr*GP_AP + mc + 0] = h; AL[kr*GP_AP + mc + 0] = l;
            split_tf32_f(ra[p].y, h, l); AH[kr*GP_AP + mc + 1] = h; AL[kr*GP_AP + mc + 1] = l;
            split_tf32_f(ra[p].z, h, l); AH[kr*GP_AP + mc + 2] = h; AL[kr*GP_AP + mc + 2] = l;
            split_tf32_f(ra[p].w, h, l); AH[kr*GP_AP + mc + 3] = h; AL[kr*GP_AP + mc + 3] = l;
        }
        #pragma unroll
        for (int p = 0; p < 2; p++) {
            int idx = tid + p * 256;
            int r   = idx >> 3;
            int kc  = (idx & 7) << 2;
            float h, l;
            split_tf32_f(rb[p].x, h, l); BH[r*GP_BP + kc + 0] = h; BL[r*GP_BP + kc + 0] = l;
            split_tf32_f(rb[p].y, h, l); BH[r*GP_BP + kc + 1] = h; BL[r*GP_BP + kc + 1] = l;
            split_tf32_f(rb[p].z, h, l); BH[r*GP_BP + kc + 2] = h; BL[r*GP_BP + kc + 2] = l;
            split_tf32_f(rb[p].w, h, l); BH[r*GP_BP + kc + 3] = h; BL[r*GP_BP + kc + 3] = l;
        }
    };

    float acc[2][4][4];
    #pragma unroll
    for (int i = 0; i < 2; i++)
        #pragma unroll
        for (int j = 0; j < 4; j++)
            #pragma unroll
            for (int q = 0; q < 4; q++) acc[i][j][q] = 0.f;

    const int NC = EE / 32;   // 24
    prefetch(0);
    stage_store(0);
    __syncthreads();

    for (int c = 0; c < NC; c++) {
        if (c + 1 < NC) prefetch((c + 1) * 32);

        const float* AH = sp + (c & 1) * GP_STAGE + GP_AHo;
        const float* AL = sp + (c & 1) * GP_STAGE + GP_ALo;
        const float* BH = sp + (c & 1) * GP_STAGE + GP_BHo;
        const float* BL = sp + (c & 1) * GP_STAGE + GP_BLo;

        #pragma unroll
        for (int k0 = 0; k0 < 32; k0 += 8) {
            uint32_t ah[2][4], al[2][4];
            #pragma unroll
            for (int mt = 0; mt < 2; mt++) {
                int mrow = wm * 32 + mt * 16 + gid;
                const float* ph = AH + (k0 + ctid) * GP_AP + mrow;
                const float* pl = AL + (k0 + ctid) * GP_AP + mrow;
                ah[mt][0] = F2U(ph[0]);          ah[mt][1] = F2U(ph[8]);
                ah[mt][2] = F2U(ph[4*GP_AP]);    ah[mt][3] = F2U(ph[4*GP_AP + 8]);
                al[mt][0] = F2U(pl[0]);          al[mt][1] = F2U(pl[8]);
                al[mt][2] = F2U(pl[4*GP_AP]);    al[mt][3] = F2U(pl[4*GP_AP + 8]);
            }
            #pragma unroll
            for (int nt = 0; nt < 4; nt++) {
                int nrow = wn * 32 + nt * 8 + gid;
                uint32_t bh[2], bl[2];
                bh[0] = F2U(BH[nrow*GP_BP + k0 + ctid]);
                bh[1] = F2U(BH[nrow*GP_BP + k0 + ctid + 4]);
                bl[0] = F2U(BL[nrow*GP_BP + k0 + ctid]);
                bl[1] = F2U(BL[nrow*GP_BP + k0 + ctid + 4]);
                #pragma unroll
                for (int mt = 0; mt < 2; mt++) {
                    mma_tf32(acc[mt][nt], ah[mt], bh);
                    mma_tf32(acc[mt][nt], ah[mt], bl);
                    mma_tf32(acc[mt][nt], al[mt], bh);
                }
            }
        }

        if (c + 1 < NC) stage_store((c + 1) & 1);
        __syncthreads();
    }

    #pragma unroll
    for (int nt = 0; nt < 4; nt++) {
        int col = n0 + wn * 32 + nt * 8 + 2 * ctid;
        float b0 = bi[col], b1 = bi[col + 1];
        #pragma unroll
        for (int mt = 0; mt < 2; mt++) {
            int row = m0 + wm * 32 + mt * 16 + gid;
            *(float2*)(y + (size_t)row * EE + col) =
                make_float2(acc[mt][nt][0] + b0, acc[mt][nt][1] + b1);
            *(float2*)(y + (size_t)(row + 8) * EE + col) =
                make_float2(acc[mt][nt][2] + b0, acc[mt][nt][3] + b1);
        }
    }
}

// =============================================================================
// Kernel 2a: scores GEMM (round 5, unchanged — stages K=64 once).
// =============================================================================
#define SK_P 68
#define SK_AH 0
#define SK_AL 8704
#define SK_BH 17408
#define SK_BL 21760
#define SK_SMEM_FLOATS 26112
#define SK_SMEM_BYTES (SK_SMEM_FLOATS * 4)

__global__ __launch_bounds__(256) void scores_mma_kernel(float* __restrict__ probs)
{
    extern __shared__ float sp[];
    float* AH = sp + SK_AH;
    float* AL = sp + SK_AL;
    float* BH = sp + SK_BH;
    float* BL = sp + SK_BL;

    const int bh = blockIdx.z;
    const int b  = bh / NH;
    const int h  = bh % NH;
    const int m0 = blockIdx.x * 128;
    const int n0 = blockIdx.y * 64;

    const float* qp = g_q + ((size_t)b * SS) * EE + h * DD;
    const float* kp = g_k + ((size_t)b * SS) * EE + h * DD;

    const int tid  = threadIdx.x;
    const int lane = tid & 31;
    const int w8   = tid >> 5;
    const int wm   = w8 >> 1;
    const int wn   = w8 & 1;
    const int gid  = lane >> 2;
    const int ctid = lane & 3;

    #pragma unroll
    for (int p = 0; p < 8; p++) {
        int idx = tid + p * 256;
        int r   = idx >> 4;
        int kc  = (idx & 15) << 2;
        float4 v4 = *(const float4*)(qp + (size_t)(m0 + r) * EE + kc);
        float4 h4, l4;
        split_tf32_f(v4.x, h4.x, l4.x);
        split_tf32_f(v4.y, h4.y, l4.y);
        split_tf32_f(v4.z, h4.z, l4.z);
        split_tf32_f(v4.w, h4.w, l4.w);
        *(float4*)(AH + r * SK_P + kc) = h4;
        *(float4*)(AL + r * SK_P + kc) = l4;
    }
    #pragma unroll
    for (int p = 0; p < 4; p++) {
        int idx = tid + p * 256;
        int r   = idx >> 4;
        int kc  = (idx & 15) << 2;
        float4 v4 = *(const float4*)(kp + (size_t)(n0 + r) * EE + kc);
        float4 h4, l4;
        split_tf32_f(v4.x, h4.x, l4.x);
        split_tf32_f(v4.y, h4.y, l4.y);
        split_tf32_f(v4.z, h4.z, l4.z);
        split_tf32_f(v4.w, h4.w, l4.w);
        *(float4*)(BH + r * SK_P + kc) = h4;
        *(float4*)(BL + r * SK_P + kc) = l4;
    }
    __syncthreads();

    float acc[2][4][4];
    #pragma unroll
    for (int i = 0; i < 2; i++)
        #pragma unroll
        for (int j = 0; j < 4; j++)
            #pragma unroll
            for (int q = 0; q < 4; q++) acc[i][j][q] = 0.f;

    #pragma unroll
    for (int k0 = 0; k0 < 64; k0 += 8) {
        uint32_t ah[2][4], al[2][4];
        #pragma unroll
        for (int mt = 0; mt < 2; mt++) {
            int mrow = wm * 32 + mt * 16 + gid;
            const float* ph = AH + mrow * SK_P + k0 + ctid;
            const float* pl = AL + mrow * SK_P + k0 + ctid;
            ah[mt][0] = F2U(ph[0]);            ah[mt][1] = F2U(ph[8*SK_P]);
            ah[mt][2] = F2U(ph[4]);            ah[mt][3] = F2U(ph[8*SK_P + 4]);
            al[mt][0] = F2U(pl[0]);            al[mt][1] = F2U(pl[8*SK_P]);
            al[mt][2] = F2U(pl[4]);            al[mt][3] = F2U(pl[8*SK_P + 4]);
        }
        #pragma unroll
        for (int nt = 0; nt < 4; nt++) {
            int nrow = wn * 32 + nt * 8 + gid;
            uint32_t bh_[2], bl_[2];
            bh_[0] = F2U(BH[nrow*SK_P + k0 + ctid]);
            bh_[1] = F2U(BH[nrow*SK_P + k0 + ctid + 4]);
            bl_[0] = F2U(BL[nrow*SK_P + k0 + ctid]);
            bl_[1] = F2U(BL[nrow*SK_P + k0 + ctid + 4]);
            #pragma unroll
            for (int mt = 0; mt < 2; mt++) {
                mma_tf32(acc[mt][nt], ah[mt], bh_);
                mma_tf32(acc[mt][nt], ah[mt], bl_);
                mma_tf32(acc[mt][nt], al[mt], bh_);
            }
        }
    }

    float* pbase = probs + (size_t)bh * SS * SS;
    #pragma unroll
    for (int mt = 0; mt < 2; mt++)
        #pragma unroll
        for (int nt = 0; nt < 4; nt++) {
            int row = m0 + wm * 32 + mt * 16 + gid;
            int col = n0 + wn * 32 + nt * 8 + 2 * ctid;
            *(float2*)(pbase + (size_t)row * SS + col) =
                make_float2(acc[mt][nt][0] * 0.125f, acc[mt][nt][1] * 0.125f);
            *(float2*)(pbase + (size_t)(row + 8) * SS + col) =
                make_float2(acc[mt][nt][2] * 0.125f, acc[mt][nt][3] * 0.125f);
        }
}

// =============================================================================
// Kernel 2b: in-place row softmax (round 5, unchanged).
// =============================================================================
__global__ __launch_bounds__(256) void softmax_kernel(float* __restrict__ probs)
{
    const int warp = threadIdx.x >> 5;
    const int lane = threadIdx.x & 31;
    const size_t row = (size_t)blockIdx.x * 8 + warp;

    float4* rp = (float4*)(probs + row * SS);

    float4 v[8];
    #pragma unroll
    for (int i = 0; i < 8; i++) v[i] = rp[lane + 32 * i];

    float mx = -3.4e38f;
    #pragma unroll
    for (int i = 0; i < 8; i++)
        mx = fmaxf(mx, fmaxf(fmaxf(v[i].x, v[i].y), fmaxf(v[i].z, v[i].w)));
    #pragma unroll
    for (int o = 16; o > 0; o >>= 1)
        mx = fmaxf(mx, __shfl_xor_sync(0xFFFFFFFFu, mx, o));

    float sum = 0.f;
    #pragma unroll
    for (int i = 0; i < 8; i++) {
        v[i].x = __expf(v[i].x - mx);
        v[i].y = __expf(v[i].y - mx);
        v[i].z = __expf(v[i].z - mx);
        v[i].w = __expf(v[i].w - mx);
        sum += v[i].x + v[i].y + v[i].z + v[i].w;
    }
    #pragma unroll
    for (int o = 16; o > 0; o >>= 1)
        sum += __shfl_xor_sync(0xFFFFFFFFu, sum, o);

    float inv = 1.f / sum;
    #pragma unroll
    for (int i = 0; i < 8; i++) {
        v[i].x *= inv; v[i].y *= inv; v[i].z *= inv; v[i].w *= inv;
        rp[lane + 32 * i] = v[i];
    }
}

// =============================================================================
// Kernel 2c: ctx GEMM, DOUBLE-BUFFERED k-loop.
//   ctx[q,d] = P[q,:] . V[:,d]  per (b,h).  128m x 64n, K=1024 in 32-chunks.
// =============================================================================
#define CX_AP 36
#define CX_BP 68
#define CX_AHo 0
#define CX_ALo 4608
#define CX_BHo 9216
#define CX_BLo 11392
#define CX_STAGE 13568
#define CX_SMEM_BYTES (2 * CX_STAGE * 4)   // 108544

__global__ __launch_bounds__(256) void ctx_mma_kernel(const float* __restrict__ probs)
{
    extern __shared__ float sp[];

    const int bh = blockIdx.z;
    const int b  = bh / NH;
    const int h  = bh % NH;
    const int m0 = blockIdx.x * 128;

    const float* pb = probs + (size_t)bh * SS * SS;
    const float* vb = g_v + ((size_t)b * SS) * EE + h * DD;

    const int tid  = threadIdx.x;
    const int lane = tid & 31;
    const int w8   = tid >> 5;
    const int wm   = w8 >> 1;
    const int wn   = w8 & 1;
    const int gid  = lane >> 2;
    const int ctid = lane & 3;

    float4 ra[4], rb[2];

    auto prefetch = [&](int kg) {
        #pragma unroll
        for (int p = 0; p < 4; p++) {
            int idx = tid + p * 256;
            int r   = idx >> 3;
            int kc  = (idx & 7) << 2;
            ra[p] = *(const float4*)(pb + (size_t)(m0 + r) * SS + kg + kc);
        }
        #pragma unroll
        for (int p = 0; p < 2; p++) {
            int idx = tid + p * 256;
            int r   = idx >> 4;
            int d4  = (idx & 15) << 2;
            rb[p] = *(const float4*)(vb + (size_t)(kg + r) * EE + d4);
        }
    };
    auto stage_store = [&](int buf) {
        float* AH = sp + buf * CX_STAGE + CX_AHo;
        float* AL = sp + buf * CX_STAGE + CX_ALo;
        float* BH = sp + buf * CX_STAGE + CX_BHo;
        float* BL = sp + buf * CX_STAGE + CX_BLo;
        #pragma unroll
        for (int p = 0; p < 4; p++) {
            int idx = tid + p * 256;
            int r   = idx >> 3;
            int kc  = (idx & 7) << 2;
            float h, l;
            split_tf32_f(ra[p].x, h, l); AH[r*CX_AP + kc + 0] = h; AL[r*CX_AP + kc + 0] = l;
            split_tf32_f(ra[p].y, h, l); AH[r*CX_AP + kc + 1] = h; AL[r*CX_AP + kc + 1] = l;
            split_tf32_f(ra[p].z, h, l); AH[r*CX_AP + kc + 2] = h; AL[r*CX_AP + kc + 2] = l;
            split_tf32_f(ra[p].w, h, l); AH[r*CX_AP + kc + 3] = h; AL[r*CX_AP + kc + 3] = l;
        }
        #pragma unroll
        for (int p = 0; p < 2; p++) {
            int idx = tid + p * 256;
            int r   = idx >> 4;
            int d4  = (idx & 15) << 2;
            float4 h4, l4;
            split_tf32_f(rb[p].x, h4.x, l4.x);
            split_tf32_f(rb[p].y, h4.y, l4.y);
            split_tf32_f(rb[p].z, h4.z, l4.z);
            split_tf32_f(rb[p].w, h4.w, l4.w);
            *(float4*)(BH + r * CX_BP + d4) = h4;
            *(float4*)(BL + r * CX_BP + d4) = l4;
        }
    };

    float acc[2][4][4];
    #pragma unroll
    for (int i = 0; i < 2; i++)
        #pragma unroll
        for (int j = 0; j < 4; j++)
            #pragma unroll
            for (int q = 0; q < 4; q++) acc[i][j][q] = 0.f;

    const int NC = SS / 32;   // 32
    prefetch(0);
    stage_store(0);
    __syncthreads();

    for (int c = 0; c < NC; c++) {
        if (c + 1 < NC) prefetch((c + 1) * 32);

        const float* AH = sp + (c & 1) * CX_STAGE + CX_AHo;
        const float* AL = sp + (c & 1) * CX_STAGE + CX_ALo;
        const float* BH = sp + (c & 1) * CX_STAGE + CX_BHo;
        const float* BL = sp + (c & 1) * CX_STAGE + CX_BLo;

        #pragma unroll
        for (int k0 = 0; k0 < 32; k0 += 8) {
            uint32_t ah[2][4], al[2][4];
            #pragma unroll
            for (int mt = 0; mt < 2; mt++) {
                int mrow = wm * 32 + mt * 16 + gid;
                const float* ph = AH + mrow * CX_AP + k0 + ctid;
                const float* pl = AL + mrow * CX_AP + k0 + ctid;
                ah[mt][0] = F2U(ph[0]);            ah[mt][1] = F2U(ph[8*CX_AP]);
                ah[mt][2] = F2U(ph[4]);            ah[mt][3] = F2U(ph[8*CX_AP + 4]);
                al[mt][0] = F2U(pl[0]);            al[mt][1] = F2U(pl[8*CX_AP]);
                al[mt][2] = F2U(pl[4]);            al[mt][3] = F2U(pl[8*CX_AP + 4]);
            }
            #pragma unroll
            for (int nt = 0; nt < 4; nt++) {
                int ncol = wn * 32 + nt * 8 + gid;
                uint32_t bh_[2], bl_[2];
                bh_[0] = F2U(BH[(k0 + ctid) * CX_BP + ncol]);
                bh_[1] = F2U(BH[(k0 + ctid + 4) * CX_BP + ncol]);
                bl_[0] = F2U(BL[(k0 + ctid) * CX_BP + ncol]);
                bl_[1] = F2U(BL[(k0 + ctid + 4) * CX_BP + ncol]);
                #pragma unroll
                for (int mt = 0; mt < 2; mt++) {
                    mma_tf32(acc[mt][nt], ah[mt], bh_);
                    mma_tf32(acc[mt][nt], ah[mt], bl_);
                    mma_tf32(acc[mt][nt], al[mt], bh_);
                }
            }
        }

        if (c + 1 < NC) stage_store((c + 1) & 1);
        __syncthreads();
    }

    #pragma unroll
    for (int mt = 0; mt < 2; mt++)
        #pragma unroll
        for (int nt = 0; nt < 4; nt++) {
            int row = m0 + wm * 32 + mt * 16 + gid;
            int col = wn * 32 + nt * 8 + 2 * ctid;
            float* op = g_ctx + ((size_t)b * SS + row) * EE + h * DD + col;
            *(float2*)op = make_float2(acc[mt][nt][0], acc[mt][nt][1]);
            *(float2*)(op + (size_t)8 * EE) = make_float2(acc[mt][nt][2], acc[mt][nt][3]);
        }
}

// =============================================================================
// Kernel 3: output projection, DOUBLE-BUFFERED k-loop.
// =============================================================================
#define GF_AP 36
#define GF_AHo 0
#define GF_ALo 4608
#define GF_BHo 9216
#define GF_BLo 11520
#define GF_STAGE 13824
#define GF_SMEM_BYTES (2 * GF_STAGE * 4)   // 110592

__global__ __launch_bounds__(256) void fc_mma_kernel(
    const float* __restrict__ fcw, const float* __restrict__ fcb,
    float* __restrict__ out)
{
    extern __shared__ float sp[];

    const int b  = blockIdx.z;
    const int m0 = blockIdx.x * 128;
    const int n0 = blockIdx.y * 64;

    const float* ctx = g_ctx + (size_t)b * SS * EE;

    const int tid  = threadIdx.x;
    const int lane = tid & 31;
    const int w8   = tid >> 5;
    const int wm   = w8 >> 1;
    const int wn   = w8 & 1;
    const int gid  = lane >> 2;
    const int ctid = lane & 3;

    float4 ra[4], rb[2];

    auto prefetch = [&](int kg) {
        #pragma unroll
        for (int p = 0; p < 4; p++) {
            int idx = tid + p * 256;
            int r   = idx >> 3;
            int kc  = (idx & 7) << 2;
            ra[p] = *(const float4*)(fcw + (size_t)(m0 + r) * EE + kg + kc);
        }
        #pragma unroll
        for (int p = 0; p < 2; p++) {
            int idx = tid + p * 256;
            int r   = idx >> 3;
            int kc  = (idx & 7) << 2;
            rb[p] = *(const float4*)(ctx + (size_t)(n0 + r) * EE + kg + kc);
        }
    };
    auto stage_store = [&](int buf) {
        float* AH = sp + buf * GF_STAGE + GF_AHo;
        float* AL = sp + buf * GF_STAGE + GF_ALo;
        float* BH = sp + buf * GF_STAGE + GF_BHo;
        float* BL = sp + buf * GF_STAGE + GF_BLo;
        #pragma unroll
        for (int p = 0; p < 4; p++) {
            int idx = tid + p * 256;
            int r   = idx >> 3;
            int kc  = (idx & 7) << 2;
            float h, l;
            split_tf32_f(ra[p].x, h, l); AH[r*GF_AP + kc + 0] = h; AL[r*GF_AP + kc + 0] = l;
            split_tf32_f(ra[p].y, h, l); AH[r*GF_AP + kc + 1] = h; AL[r*GF_AP + kc + 1] = l;
            split_tf32_f(ra[p].z, h, l); AH[r*GF_AP + kc + 2] = h; AL[r*GF_AP + kc + 2] = l;
            split_tf32_f(ra[p].w, h, l); AH[r*GF_AP + kc + 3] = h; AL[r*GF_AP + kc + 3] = l;
        }
        #pragma unroll
        for (int p = 0; p < 2; p++) {
            int idx = tid + p * 256;
            int r   = idx >> 3;
            int kc  = (idx & 7) << 2;
            float h, l;
            split_tf32_f(rb[p].x, h, l); BH[r*GF_AP + kc + 0] = h; BL[r*GF_AP + kc + 0] = l;
            split_tf32_f(rb[p].y, h, l); BH[r*GF_AP + kc + 1] = h; BL[r*GF_AP + kc + 1] = l;
            split_tf32_f(rb[p].z, h, l); BH[r*GF_AP + kc + 2] = h; BL[r*GF_AP + kc + 2] = l;
            split_tf32_f(rb[p].w, h, l); BH[r*GF_AP + kc + 3] = h; BL[r*GF_AP + kc + 3] = l;
        }
    };

    float acc[2][4][4];
    #pragma unroll
    for (int i = 0; i < 2; i++)
        #pragma unroll
        for (int j = 0; j < 4; j++)
            #pragma unroll
            for (int q = 0; q < 4; q++) acc[i][j][q] = 0.f;

    const int NC = EE / 32;   // 24
    prefetch(0);
    stage_store(0);
    __syncthreads();

    for (int c = 0; c < NC; c++) {
        if (c + 1 < NC) prefetch((c + 1) * 32);

        const float* AH = sp + (c & 1) * GF_STAGE + GF_AHo;
        const float* AL = sp + (c & 1) * GF_STAGE + GF_ALo;
        const float* BH = sp + (c & 1) * GF_STAGE + GF_BHo;
        const float* BL = sp + (c & 1) * GF_STAGE + GF_BLo;

        #pragma unroll
        for (int k0 = 0; k0 < 32; k0 += 8) {
            uint32_t ah[2][4], al[2][4];
            #pragma unroll
            for (int mt = 0; mt < 2; mt++) {
                int mrow = wm * 32 + mt * 16 + gid;
                const float* ph = AH + mrow * GF_AP + k0 + ctid;
                const float* pl = AL + mrow * GF_AP + k0 + ctid;
                ah[mt][0] = F2U(ph[0]);              ah[mt][1] = F2U(ph[8*GF_AP]);
                ah[mt][2] = F2U(ph[4]);              ah[mt][3] = F2U(ph[8*GF_AP + 4]);
                al[mt][0] = F2U(pl[0]);              al[mt][1] = F2U(pl[8*GF_AP]);
                al[mt][2] = F2U(pl[4]);              al[mt][3] = F2U(pl[8*GF_AP + 4]);
            }
            #pragma unroll
            for (int nt = 0; nt < 4; nt++) {
                int nrow = wn * 32 + nt * 8 + gid;
                uint32_t bh[2], bl[2];
                bh[0] = F2U(BH[nrow*GF_AP + k0 + ctid]);
                bh[1] = F2U(BH[nrow*GF_AP + k0 + ctid + 4]);
                bl[0] = F2U(BL[nrow*GF_AP + k0 + ctid]);
                bl[1] = F2U(BL[nrow*GF_AP + k0 + ctid + 4]);
                #pragma unroll
                for (int mt = 0; mt < 2; mt++) {
                    mma_tf32(acc[mt][nt], ah[mt], bh);
                    mma_tf32(acc[mt][nt], ah[mt], bl);
                    mma_tf32(acc[mt][nt], al[mt], bh);
                }
            }
        }

        if (c + 1 < NC) stage_store((c + 1) & 1);
        __syncthreads();
    }

    #pragma unroll
    for (int mt = 0; mt < 2; mt++) {
        int row = m0 + wm * 32 + mt * 16 + gid;
        float fb0 = fcb[row];
        float fb1 = fcb[row + 8];
        #pragma unroll
        for (int nt = 0; nt < 4; nt++) {
            int col = n0 + wn * 32 + nt * 8 + 2 * ctid;
            *(float2*)(out + ((size_t)b * EE + row) * SS + col) =
                make_float2(acc[mt][nt][0] + fb0, acc[mt][nt][1] + fb0);
            *(float2*)(out + ((size_t)b * EE + row + 8) * SS + col) =
                make_float2(acc[mt][nt][2] + fb1, acc[mt][nt][3] + fb1);
        }
    }
}

// =============================================================================
extern "C" void kernel_launch(void* const* d_in, const int* in_sizes, int n_in,
                              void* d_out, int out_size)
{
    const float* q_img = (const float*)d_in[0];
    const float* k_img = (const float*)d_in[1];
    const float* v_img = (const float*)d_in[2];
    const float* wq_w  = (const float*)d_in[3];
    const float* wq_b  = (const float*)d_in[4];
    const float* wk_w  = (const float*)d_in[5];
    const float* wk_b  = (const float*)d_in[6];
    const float* wv_w  = (const float*)d_in[7];
    const float* wv_b  = (const float*)d_in[8];
    const float* fc_w  = (const float*)d_in[9];
    const float* fc_b  = (const float*)d_in[10];

    float* out   = (float*)d_out;
    float* probs = out + (size_t)BB * EE * SS;   // tuple output: (out, probs)

    cudaFuncSetAttribute(proj_mma_kernel, cudaFuncAttributeMaxDynamicSharedMemorySize,
                         GP_SMEM_BYTES);
    cudaFuncSetAttribute(scores_mma_kernel, cudaFuncAttributeMaxDynamicSharedMemorySize,
                         SK_SMEM_BYTES);
    cudaFuncSetAttribute(ctx_mma_kernel, cudaFuncAttributeMaxDynamicSharedMemorySize,
                         CX_SMEM_BYTES);
    cudaFuncSetAttribute(fc_mma_kernel, cudaFuncAttributeMaxDynamicSharedMemorySize,
                         GF_SMEM_BYTES);

    // 1) QKV projections
    proj_mma_kernel<<<dim3(SS / 128, EE / 64, 3 * BB), 256, GP_SMEM_BYTES>>>(
        q_img, k_img, v_img, wq_w, wk_w, wv_w, wq_b, wk_b, wv_b);

    // 2a) scores -> raw into probs buffer
    scores_mma_kernel<<<dim3(SS / 128, SS / 64, BB * NH), 256, SK_SMEM_BYTES>>>(probs);

    // 2b) in-place softmax over probs rows
    softmax_kernel<<<(BB * NH * SS) / 8, 256>>>(probs);

    // 2c) ctx = P @ V
    ctx_mma_kernel<<<dim3(SS / 128, 1, BB * NH), 256, CX_SMEM_BYTES>>>(probs);

    // 3) output projection
    fc_mma_kernel<<<dim3(EE / 128, SS / 64, BB), 256, GF_SMEM_BYTES>>>(fc_w, fc_b, out);
}

// round 7
// speedup vs baseline: 1.6020x; 1.6020x over previous
#include <cuda_runtime.h>
#include <cuda_bf16.h>
#include <cstdint>

// Problem dims
#define BB 8
#define SS 1024          // IMG*IMG
#define EE 768           // D_EMBED == D_MODEL
#define NH 12
#define DD 64

// ---------------- scratch (device globals; no allocs allowed) ----------------
__device__ float g_q[BB * SS * EE];
__device__ float g_k[BB * SS * EE];
__device__ float g_v[BB * SS * EE];
__device__ float g_ctx[BB * SS * EE];

// =============================================================================
// bf16 split helpers: x = hi + lo, both bf16. Packed pairs along k:
// low 16 bits = lower k index (matches mma fragment element order).
// =============================================================================
__device__ __forceinline__ void split2_bf16(float x0, float x1,
                                            uint32_t& hw, uint32_t& lw) {
    __nv_bfloat162 h = __floats2bfloat162_rn(x0, x1);
    float2 hf = __bfloat1622float2(h);
    __nv_bfloat162 l = __floats2bfloat162_rn(x0 - hf.x, x1 - hf.y);
    hw = *reinterpret_cast<uint32_t*>(&h);
    lw = *reinterpret_cast<uint32_t*>(&l);
}

__device__ __forceinline__ void mma_bf16(float* d, const uint32_t* a, const uint32_t* b) {
    asm volatile(
        "mma.sync.aligned.m16n8k16.row.col.f32.bf16.bf16.f32 "
        "{%0,%1,%2,%3}, {%4,%5,%6,%7}, {%8,%9}, {%0,%1,%2,%3};"
        : "+f"(d[0]), "+f"(d[1]), "+f"(d[2]), "+f"(d[3])
        : "r"(a[0]), "r"(a[1]), "r"(a[2]), "r"(a[3]),
          "r"(b[0]), "r"(b[1]));
}

// 3-term split-bf16 product: ah*bh + ah*bl + al*bh
#define MMA3(accp, ah_, al_, bh_, bl_) \
    do { mma_bf16(accp, ah_, bh_); mma_bf16(accp, ah_, bl_); mma_bf16(accp, al_, bh_); } while (0)

// =============================================================================
// Kernel 1: QKV projection, split-bf16 mma.
//   Y[s,o] = sum_c X[b][c][s] * W[o][c] + bias[o]
// A (X^T, k-major source) -> packed k-major planes At[16kw][128m] pitch 136w.
// B (W, k-contig)         -> packed Bs[64n][16kw] pitch 20w.
// 128m x 64n block, 32k chunks, 8 warps = 4(m) x 2(n).
// =============================================================================
#define GP_AP 136
#define GP_BP 20
#define GP_AHo 0
#define GP_ALo 2176
#define GP_BHo 4352
#define GP_BLo 5632
#define GP_SMEM_WORDS 6912
#define GP_SMEM_BYTES (GP_SMEM_WORDS * 4)   // 27648

__global__ __launch_bounds__(256) void proj_mma_kernel(
    const float* __restrict__ xq, const float* __restrict__ xk, const float* __restrict__ xv,
    const float* __restrict__ wq, const float* __restrict__ wk, const float* __restrict__ wv,
    const float* __restrict__ bq, const float* __restrict__ bk, const float* __restrict__ bv)
{
    extern __shared__ uint32_t su[];
    uint32_t* AH = su + GP_AHo;
    uint32_t* AL = su + GP_ALo;
    uint32_t* BH = su + GP_BHo;
    uint32_t* BL = su + GP_BLo;

    const int mat = blockIdx.z >> 3;
    const int b   = blockIdx.z & 7;

    const float* x; const float* w; const float* bi; float* y;
    if (mat == 0)      { x = xq; w = wq; bi = bq; y = g_q; }
    else if (mat == 1) { x = xk; w = wk; bi = bk; y = g_k; }
    else               { x = xv; w = wv; bi = bv; y = g_v; }
    x += (size_t)b * EE * SS;
    y += (size_t)b * SS * EE;

    const int m0 = blockIdx.x * 128;
    const int n0 = blockIdx.y * 64;

    const int tid  = threadIdx.x;
    const int lane = tid & 31;
    const int w8   = tid >> 5;
    const int wm   = w8 >> 1;
    const int wn   = w8 & 1;
    const int gid  = lane >> 2;
    const int ctid = lane & 3;

    float acc[2][4][4];
    #pragma unroll
    for (int i = 0; i < 2; i++)
        #pragma unroll
        for (int j = 0; j < 4; j++)
            #pragma unroll
            for (int q = 0; q < 4; q++) acc[i][j][q] = 0.f;

    for (int kg = 0; kg < EE; kg += 32) {
        __syncthreads();
        // stage A: X rows [kg..kg+32) x cols [m0..m0+128) -> At[kw][m] packed
        #pragma unroll
        for (int p = 0; p < 2; p++) {
            int idx = tid + p * 256;            // 0..511
            int j   = idx >> 5;                 // kw 0..15 (k pair = kg+2j, kg+2j+1)
            int m4  = (idx & 31) << 2;          // m offset
            const float* xr = x + (size_t)(kg + 2 * j) * SS + m0 + m4;
            float4 ra = *(const float4*)xr;
            float4 rb = *(const float4*)(xr + SS);
            uint4 hv, lv;
            split2_bf16(ra.x, rb.x, hv.x, lv.x);
            split2_bf16(ra.y, rb.y, hv.y, lv.y);
            split2_bf16(ra.z, rb.z, hv.z, lv.z);
            split2_bf16(ra.w, rb.w, hv.w, lv.w);
            *(uint4*)(AH + j * GP_AP + m4) = hv;
            *(uint4*)(AL + j * GP_AP + m4) = lv;
        }
        // stage B: W rows [n0..n0+64) x k [kg..kg+32) -> Bs[n][kw] packed
        {
            int r  = tid >> 2;                  // 0..63
            int kq = (tid & 3) << 3;            // k float offset 0,8,16,24
            const float* wr = w + (size_t)(n0 + r) * EE + kg + kq;
            float4 b0 = *(const float4*)wr;
            float4 b1 = *(const float4*)(wr + 4);
            uint4 hv, lv;
            split2_bf16(b0.x, b0.y, hv.x, lv.x);
            split2_bf16(b0.z, b0.w, hv.y, lv.y);
            split2_bf16(b1.x, b1.y, hv.z, lv.z);
            split2_bf16(b1.z, b1.w, hv.w, lv.w);
            *(uint4*)(BH + r * GP_BP + (tid & 3) * 4) = hv;
            *(uint4*)(BL + r * GP_BP + (tid & 3) * 4) = lv;
        }
        __syncthreads();

        #pragma unroll
        for (int kwb = 0; kwb < 16; kwb += 8) {
            uint32_t ah[2][4], al[2][4];
            #pragma unroll
            for (int mt = 0; mt < 2; mt++) {
                int mrow = wm * 32 + mt * 16 + gid;
                const uint32_t* ph = AH + (kwb + ctid) * GP_AP + mrow;
                const uint32_t* pl = AL + (kwb + ctid) * GP_AP + mrow;
                ah[mt][0] = ph[0];          ah[mt][1] = ph[8];
                ah[mt][2] = ph[4*GP_AP];    ah[mt][3] = ph[4*GP_AP + 8];
                al[mt][0] = pl[0];          al[mt][1] = pl[8];
                al[mt][2] = pl[4*GP_AP];    al[mt][3] = pl[4*GP_AP + 8];
            }
            #pragma unroll
            for (int nt = 0; nt < 4; nt++) {
                int nrow = wn * 32 + nt * 8 + gid;
                const uint32_t* pbh = BH + nrow * GP_BP + kwb + ctid;
                const uint32_t* pbl = BL + nrow * GP_BP + kwb + ctid;
                uint32_t bh_[2] = { pbh[0], pbh[4] };
                uint32_t bl_[2] = { pbl[0], pbl[4] };
                #pragma unroll
                for (int mt = 0; mt < 2; mt++)
                    MMA3(acc[mt][nt], ah[mt], al[mt], bh_, bl_);
            }
        }
    }

    #pragma unroll
    for (int nt = 0; nt < 4; nt++) {
        int col = n0 + wn * 32 + nt * 8 + 2 * ctid;
        float b0 = bi[col], b1 = bi[col + 1];
        #pragma unroll
        for (int mt = 0; mt < 2; mt++) {
            int row = m0 + wm * 32 + mt * 16 + gid;
            *(float2*)(y + (size_t)row * EE + col) =
                make_float2(acc[mt][nt][0] + b0, acc[mt][nt][1] + b1);
            *(float2*)(y + (size_t)(row + 8) * EE + col) =
                make_float2(acc[mt][nt][2] + b0, acc[mt][nt][3] + b1);
        }
    }
}

// =============================================================================
// Kernel 2a: scores GEMM, split-bf16.  S = (Q K^T)/8 raw into probs.
// A=Q[m][k], B=K[n][k] both k-contig -> packed [row][kw] pitch 36w, K=64
// staged once (32 kw).
// =============================================================================
#define SK_P 36
#define SK_AHo 0
#define SK_ALo 4608
#define SK_BHo 9216
#define SK_BLo 11520
#define SK_SMEM_WORDS 13824
#define SK_SMEM_BYTES (SK_SMEM_WORDS * 4)   // 55296

__global__ __launch_bounds__(256) void scores_mma_kernel(float* __restrict__ probs)
{
    extern __shared__ uint32_t su[];
    uint32_t* AH = su + SK_AHo;
    uint32_t* AL = su + SK_ALo;
    uint32_t* BH = su + SK_BHo;
    uint32_t* BL = su + SK_BLo;

    const int bh = blockIdx.z;
    const int b  = bh / NH;
    const int h  = bh % NH;
    const int m0 = blockIdx.x * 128;
    const int n0 = blockIdx.y * 64;

    const float* qp = g_q + ((size_t)b * SS) * EE + h * DD;
    const float* kp = g_k + ((size_t)b * SS) * EE + h * DD;

    const int tid  = threadIdx.x;
    const int lane = tid & 31;
    const int w8   = tid >> 5;
    const int wm   = w8 >> 1;
    const int wn   = w8 & 1;
    const int gid  = lane >> 2;
    const int ctid = lane & 3;

    // stage A (Q): 128 rows x 64 k -> [m][kw]
    #pragma unroll
    for (int p = 0; p < 4; p++) {
        int idx = tid + p * 256;         // 0..1023
        int r   = idx >> 3;
        int kq  = (idx & 7) << 3;        // k float offset
        const float* qr = qp + (size_t)(m0 + r) * EE + kq;
        float4 a0 = *(const float4*)qr;
        float4 a1 = *(const float4*)(qr + 4);
        uint4 hv, lv;
        split2_bf16(a0.x, a0.y, hv.x, lv.x);
        split2_bf16(a0.z, a0.w, hv.y, lv.y);
        split2_bf16(a1.x, a1.y, hv.z, lv.z);
        split2_bf16(a1.z, a1.w, hv.w, lv.w);
        *(uint4*)(AH + r * SK_P + (idx & 7) * 4) = hv;
        *(uint4*)(AL + r * SK_P + (idx & 7) * 4) = lv;
    }
    // stage B (K): 64 rows x 64 k
    #pragma unroll
    for (int p = 0; p < 2; p++) {
        int idx = tid + p * 256;         // 0..511
        int r   = idx >> 3;
        int kq  = (idx & 7) << 3;
        const float* kr = kp + (size_t)(n0 + r) * EE + kq;
        float4 b0 = *(const float4*)kr;
        float4 b1 = *(const float4*)(kr + 4);
        uint4 hv, lv;
        split2_bf16(b0.x, b0.y, hv.x, lv.x);
        split2_bf16(b0.z, b0.w, hv.y, lv.y);
        split2_bf16(b1.x, b1.y, hv.z, lv.z);
        split2_bf16(b1.z, b1.w, hv.w, lv.w);
        *(uint4*)(BH + r * SK_P + (idx & 7) * 4) = hv;
        *(uint4*)(BL + r * SK_P + (idx & 7) * 4) = lv;
    }
    __syncthreads();

    float acc[2][4][4];
    #pragma unroll
    for (int i = 0; i < 2; i++)
        #pragma unroll
        for (int j = 0; j < 4; j++)
            #pragma unroll
            for (int q = 0; q < 4; q++) acc[i][j][q] = 0.f;

    #pragma unroll
    for (int kwb = 0; kwb < 32; kwb += 8) {
        uint32_t ah[2][4], al[2][4];
        #pragma unroll
        for (int mt = 0; mt < 2; mt++) {
            int mrow = wm * 32 + mt * 16 + gid;
            const uint32_t* ph = AH + mrow * SK_P + kwb + ctid;
            const uint32_t* pl = AL + mrow * SK_P + kwb + ctid;
            ah[mt][0] = ph[0];          ah[mt][1] = ph[8*SK_P];
            ah[mt][2] = ph[4];          ah[mt][3] = ph[8*SK_P + 4];
            al[mt][0] = pl[0];          al[mt][1] = pl[8*SK_P];
            al[mt][2] = pl[4];          al[mt][3] = pl[8*SK_P + 4];
        }
        #pragma unroll
        for (int nt = 0; nt < 4; nt++) {
            int nrow = wn * 32 + nt * 8 + gid;
            const uint32_t* pbh = BH + nrow * SK_P + kwb + ctid;
            const uint32_t* pbl = BL + nrow * SK_P + kwb + ctid;
            uint32_t bh_[2] = { pbh[0], pbh[4] };
            uint32_t bl_[2] = { pbl[0], pbl[4] };
            #pragma unroll
            for (int mt = 0; mt < 2; mt++)
                MMA3(acc[mt][nt], ah[mt], al[mt], bh_, bl_);
        }
    }

    float* pbase = probs + (size_t)bh * SS * SS;
    #pragma unroll
    for (int mt = 0; mt < 2; mt++)
        #pragma unroll
        for (int nt = 0; nt < 4; nt++) {
            int row = m0 + wm * 32 + mt * 16 + gid;
            int col = n0 + wn * 32 + nt * 8 + 2 * ctid;
            *(float2*)(pbase + (size_t)row * SS + col) =
                make_float2(acc[mt][nt][0] * 0.125f, acc[mt][nt][1] * 0.125f);
            *(float2*)(pbase + (size_t)(row + 8) * SS + col) =
                make_float2(acc[mt][nt][2] * 0.125f, acc[mt][nt][3] * 0.125f);
        }
}

// =============================================================================
// Kernel 2b: in-place row softmax (unchanged).
// =============================================================================
__global__ __launch_bounds__(256) void softmax_kernel(float* __restrict__ probs)
{
    const int warp = threadIdx.x >> 5;
    const int lane = threadIdx.x & 31;
    const size_t row = (size_t)blockIdx.x * 8 + warp;

    float4* rp = (float4*)(probs + row * SS);

    float4 v[8];
    #pragma unroll
    for (int i = 0; i < 8; i++) v[i] = rp[lane + 32 * i];

    float mx = -3.4e38f;
    #pragma unroll
    for (int i = 0; i < 8; i++)
        mx = fmaxf(mx, fmaxf(fmaxf(v[i].x, v[i].y), fmaxf(v[i].z, v[i].w)));
    #pragma unroll
    for (int o = 16; o > 0; o >>= 1)
        mx = fmaxf(mx, __shfl_xor_sync(0xFFFFFFFFu, mx, o));

    float sum = 0.f;
    #pragma unroll
    for (int i = 0; i < 8; i++) {
        v[i].x = __expf(v[i].x - mx);
        v[i].y = __expf(v[i].y - mx);
        v[i].z = __expf(v[i].z - mx);
        v[i].w = __expf(v[i].w - mx);
        sum += v[i].x + v[i].y + v[i].z + v[i].w;
    }
    #pragma unroll
    for (int o = 16; o > 0; o >>= 1)
        sum += __shfl_xor_sync(0xFFFFFFFFu, sum, o);

    float inv = 1.f / sum;
    #pragma unroll
    for (int i = 0; i < 8; i++) {
        v[i].x *= inv; v[i].y *= inv; v[i].z *= inv; v[i].w *= inv;
        rp[lane + 32 * i] = v[i];
    }
}

// =============================================================================
// Kernel 2c: ctx GEMM, split-bf16.  ctx[q,d] = P[q,:] . V[:,d]  per (b,h).
// A = P[m][k] k-contig -> [m][kw] pitch 20w. B = V[k][n] -> packed k-major
// Bt[16kw][64n] pitch 72w. 128m x 64n, K=1024 in 32-chunks.
// =============================================================================
#define CX_AP 20
#define CX_BP 72
#define CX_AHo 0
#define CX_ALo 2560
#define CX_BHo 5120
#define CX_BLo 6272
#define CX_SMEM_WORDS 7424
#define CX_SMEM_BYTES (CX_SMEM_WORDS * 4)   // 29696

__global__ __launch_bounds__(256) void ctx_mma_kernel(const float* __restrict__ probs)
{
    extern __shared__ uint32_t su[];
    uint32_t* AH = su + CX_AHo;
    uint32_t* AL = su + CX_ALo;
    uint32_t* BH = su + CX_BHo;
    uint32_t* BL = su + CX_BLo;

    const int bh = blockIdx.z;
    const int b  = bh / NH;
    const int h  = bh % NH;
    const int m0 = blockIdx.x * 128;

    const float* pb = probs + (size_t)bh * SS * SS;
    const float* vb = g_v + ((size_t)b * SS) * EE + h * DD;

    const int tid  = threadIdx.x;
    const int lane = tid & 31;
    const int w8   = tid >> 5;
    const int wm   = w8 >> 1;
    const int wn   = w8 & 1;
    const int gid  = lane >> 2;
    const int ctid = lane & 3;

    float acc[2][4][4];
    #pragma unroll
    for (int i = 0; i < 2; i++)
        #pragma unroll
        for (int j = 0; j < 4; j++)
            #pragma unroll
            for (int q = 0; q < 4; q++) acc[i][j][q] = 0.f;

    for (int kg = 0; kg < SS; kg += 32) {
        __syncthreads();
        // stage A (P): 128 rows x 32 k -> [m][kw]
        #pragma unroll
        for (int p = 0; p < 2; p++) {
            int idx = tid + p * 256;         // 0..511
            int r   = idx >> 2;
            int kq  = (idx & 3) << 3;
            const float* pr = pb + (size_t)(m0 + r) * SS + kg + kq;
            float4 a0 = *(const float4*)pr;
            float4 a1 = *(const float4*)(pr + 4);
            uint4 hv, lv;
            split2_bf16(a0.x, a0.y, hv.x, lv.x);
            split2_bf16(a0.z, a0.w, hv.y, lv.y);
            split2_bf16(a1.x, a1.y, hv.z, lv.z);
            split2_bf16(a1.z, a1.w, hv.w, lv.w);
            *(uint4*)(AH + r * CX_AP + (idx & 3) * 4) = hv;
            *(uint4*)(AL + r * CX_AP + (idx & 3) * 4) = lv;
        }
        // stage B (V): 32 k-rows x 64 d -> packed k-major Bt[kw][n]
        {
            int j  = tid >> 4;               // kw 0..15
            int d4 = (tid & 15) << 2;        // d offset
            const float* vr = vb + (size_t)(kg + 2 * j) * EE + d4;
            float4 r0 = *(const float4*)vr;
            float4 r1 = *(const float4*)(vr + EE);
            uint4 hv, lv;
            split2_bf16(r0.x, r1.x, hv.x, lv.x);
            split2_bf16(r0.y, r1.y, hv.y, lv.y);
            split2_bf16(r0.z, r1.z, hv.z, lv.z);
            split2_bf16(r0.w, r1.w, hv.w, lv.w);
            *(uint4*)(BH + j * CX_BP + d4) = hv;
            *(uint4*)(BL + j * CX_BP + d4) = lv;
        }
        __syncthreads();

        #pragma unroll
        for (int kwb = 0; kwb < 16; kwb += 8) {
            uint32_t ah[2][4], al[2][4];
            #pragma unroll
            for (int mt = 0; mt < 2; mt++) {
                int mrow = wm * 32 + mt * 16 + gid;
                const uint32_t* ph = AH + mrow * CX_AP + kwb + ctid;
                const uint32_t* pl = AL + mrow * CX_AP + kwb + ctid;
                ah[mt][0] = ph[0];          ah[mt][1] = ph[8*CX_AP];
                ah[mt][2] = ph[4];          ah[mt][3] = ph[8*CX_AP + 4];
                al[mt][0] = pl[0];          al[mt][1] = pl[8*CX_AP];
                al[mt][2] = pl[4];          al[mt][3] = pl[8*CX_AP + 4];
            }
            #pragma unroll
            for (int nt = 0; nt < 4; nt++) {
                int nrow = wn * 32 + nt * 8 + gid;
                const uint32_t* pbh = BH + (kwb + ctid) * CX_BP + nrow;
                const uint32_t* pbl = BL + (kwb + ctid) * CX_BP + nrow;
                uint32_t bh_[2] = { pbh[0], pbh[4*CX_BP] };
                uint32_t bl_[2] = { pbl[0], pbl[4*CX_BP] };
                #pragma unroll
                for (int mt = 0; mt < 2; mt++)
                    MMA3(acc[mt][nt], ah[mt], al[mt], bh_, bl_);
            }
        }
    }

    #pragma unroll
    for (int mt = 0; mt < 2; mt++)
        #pragma unroll
        for (int nt = 0; nt < 4; nt++) {
            int row = m0 + wm * 32 + mt * 16 + gid;
            int col = wn * 32 + nt * 8 + 2 * ctid;
            float* op = g_ctx + ((size_t)b * SS + row) * EE + h * DD + col;
            *(float2*)op = make_float2(acc[mt][nt][0], acc[mt][nt][1]);
            *(float2*)(op + (size_t)8 * EE) = make_float2(acc[mt][nt][2], acc[mt][nt][3]);
        }
}

// =============================================================================
// Kernel 3: output projection, split-bf16.
//   out[b][o][s] = sum_c ctx[b][s][c] * fc_w[o][c] + fc_b[o]
// A = fc_w[m][k], B = ctx[n][k], both k-contig -> [row][kw] pitch 20w.
// =============================================================================
#define GF_AP 20
#define GF_AHo 0
#define GF_ALo 2560
#define GF_BHo 5120
#define GF_BLo 6400
#define GF_SMEM_WORDS 7680
#define GF_SMEM_BYTES (GF_SMEM_WORDS * 4)   // 30720

__global__ __launch_bounds__(256) void fc_mma_kernel(
    const float* __restrict__ fcw, const float* __restrict__ fcb,
    float* __restrict__ out)
{
    extern __shared__ uint32_t su[];
    uint32_t* AH = su + GF_AHo;
    uint32_t* AL = su + GF_ALo;
    uint32_t* BH = su + GF_BHo;
    uint32_t* BL = su + GF_BLo;

    const int b  = blockIdx.z;
    const int m0 = blockIdx.x * 128;
    const int n0 = blockIdx.y * 64;

    const float* ctx = g_ctx + (size_t)b * SS * EE;

    const int tid  = threadIdx.x;
    const int lane = tid & 31;
    const int w8   = tid >> 5;
    const int wm   = w8 >> 1;
    const int wn   = w8 & 1;
    const int gid  = lane >> 2;
    const int ctid = lane & 3;

    float acc[2][4][4];
    #pragma unroll
    for (int i = 0; i < 2; i++)
        #pragma unroll
        for (int j = 0; j < 4; j++)
            #pragma unroll
            for (int q = 0; q < 4; q++) acc[i][j][q] = 0.f;

    for (int kg = 0; kg < EE; kg += 32) {
        __syncthreads();
        // stage A (fc_w): 128 rows x 32 k
        #pragma unroll
        for (int p = 0; p < 2; p++) {
            int idx = tid + p * 256;
            int r   = idx >> 2;
            int kq  = (idx & 3) << 3;
            const float* ar = fcw + (size_t)(m0 + r) * EE + kg + kq;
            float4 a0 = *(const float4*)ar;
            float4 a1 = *(const float4*)(ar + 4);
            uint4 hv, lv;
            split2_bf16(a0.x, a0.y, hv.x, lv.x);
            split2_bf16(a0.z, a0.w, hv.y, lv.y);
            split2_bf16(a1.x, a1.y, hv.z, lv.z);
            split2_bf16(a1.z, a1.w, hv.w, lv.w);
            *(uint4*)(AH + r * GF_AP + (idx & 3) * 4) = hv;
            *(uint4*)(AL + r * GF_AP + (idx & 3) * 4) = lv;
        }
        // stage B (ctx): 64 rows x 32 k
        {
            int r  = tid >> 2;
            int kq = (tid & 3) << 3;
            const float* br = ctx + (size_t)(n0 + r) * EE + kg + kq;
            float4 b0 = *(const float4*)br;
            float4 b1 = *(const float4*)(br + 4);
            uint4 hv, lv;
            split2_bf16(b0.x, b0.y, hv.x, lv.x);
            split2_bf16(b0.z, b0.w, hv.y, lv.y);
            split2_bf16(b1.x, b1.y, hv.z, lv.z);
            split2_bf16(b1.z, b1.w, hv.w, lv.w);
            *(uint4*)(BH + r * GF_AP + (tid & 3) * 4) = hv;
            *(uint4*)(BL + r * GF_AP + (tid & 3) * 4) = lv;
        }
        __syncthreads();

        #pragma unroll
        for (int kwb = 0; kwb < 16; kwb += 8) {
            uint32_t ah[2][4], al[2][4];
            #pragma unroll
            for (int mt = 0; mt < 2; mt++) {
                int mrow = wm * 32 + mt * 16 + gid;
                const uint32_t* ph = AH + mrow * GF_AP + kwb + ctid;
                const uint32_t* pl = AL + mrow * GF_AP + kwb + ctid;
                ah[mt][0] = ph[0];          ah[mt][1] = ph[8*GF_AP];
                ah[mt][2] = ph[4];          ah[mt][3] = ph[8*GF_AP + 4];
                al[mt][0] = pl[0];          al[mt][1] = pl[8*GF_AP];
                al[mt][2] = pl[4];          al[mt][3] = pl[8*GF_AP + 4];
            }
            #pragma unroll
            for (int nt = 0; nt < 4; nt++) {
                int nrow = wn * 32 + nt * 8 + gid;
                const uint32_t* pbh = BH + nrow * GF_AP + kwb + ctid;
                const uint32_t* pbl = BL + nrow * GF_AP + kwb + ctid;
                uint32_t bh_[2] = { pbh[0], pbh[4] };
                uint32_t bl_[2] = { pbl[0], pbl[4] };
                #pragma unroll
                for (int mt = 0; mt < 2; mt++)
                    MMA3(acc[mt][nt], ah[mt], al[mt], bh_, bl_);
            }
        }
    }

    #pragma unroll
    for (int mt = 0; mt < 2; mt++) {
        int row = m0 + wm * 32 + mt * 16 + gid;
        float fb0 = fcb[row];
        float fb1 = fcb[row + 8];
        #pragma unroll
        for (int nt = 0; nt < 4; nt++) {
            int col = n0 + wn * 32 + nt * 8 + 2 * ctid;
            *(float2*)(out + ((size_t)b * EE + row) * SS + col) =
                make_float2(acc[mt][nt][0] + fb0, acc[mt][nt][1] + fb0);
            *(float2*)(out + ((size_t)b * EE + row + 8) * SS + col) =
                make_float2(acc[mt][nt][2] + fb1, acc[mt][nt][3] + fb1);
        }
    }
}

// =============================================================================
extern "C" void kernel_launch(void* const* d_in, const int* in_sizes, int n_in,
                              void* d_out, int out_size)
{
    const float* q_img = (const float*)d_in[0];
    const float* k_img = (const float*)d_in[1];
    const float* v_img = (const float*)d_in[2];
    const float* wq_w  = (const float*)d_in[3];
    const float* wq_b  = (const float*)d_in[4];
    const float* wk_w  = (const float*)d_in[5];
    const float* wk_b  = (const float*)d_in[6];
    const float* wv_w  = (const float*)d_in[7];
    const float* wv_b  = (const float*)d_in[8];
    const float* fc_w  = (const float*)d_in[9];
    const float* fc_b  = (const float*)d_in[10];

    float* out   = (float*)d_out;
    float* probs = out + (size_t)BB * EE * SS;   // tuple output: (out, probs)

    cudaFuncSetAttribute(proj_mma_kernel, cudaFuncAttributeMaxDynamicSharedMemorySize,
                         GP_SMEM_BYTES);
    cudaFuncSetAttribute(scores_mma_kernel, cudaFuncAttributeMaxDynamicSharedMemorySize,
                         SK_SMEM_BYTES);
    cudaFuncSetAttribute(ctx_mma_kernel, cudaFuncAttributeMaxDynamicSharedMemorySize,
                         CX_SMEM_BYTES);
    cudaFuncSetAttribute(fc_mma_kernel, cudaFuncAttributeMaxDynamicSharedMemorySize,
                         GF_SMEM_BYTES);

    // 1) QKV projections
    proj_mma_kernel<<<dim3(SS / 128, EE / 64, 3 * BB), 256, GP_SMEM_BYTES>>>(
        q_img, k_img, v_img, wq_w, wk_w, wv_w, wq_b, wk_b, wv_b);

    // 2a) scores -> raw into probs buffer
    scores_mma_kernel<<<dim3(SS / 128, SS / 64, BB * NH), 256, SK_SMEM_BYTES>>>(probs);

    // 2b) in-place softmax over probs rows
    softmax_kernel<<<(BB * NH * SS) / 8, 256>>>(probs);

    // 2c) ctx = P @ V
    ctx_mma_kernel<<<dim3(SS / 128, 1, BB * NH), 256, CX_SMEM_BYTES>>>(probs);

    // 3) output projection
    fc_mma_kernel<<<dim3(EE / 128, SS / 64, BB), 256, GF_SMEM_BYTES>>>(fc_w, fc_b, out);
}